// round 10
// baseline (speedup 1.0000x reference)
#include <cuda_runtime.h>
#include <cstdint>

// VoxelBracketPredictor_v2 — 2-kernel pipeline (R8 + occupancy-capped wave overlap):
//  k0 bounds: segment boundaries (int4 scan of sorted segment_ids)
//  k1 fused:  CTA = 8 CONTIGUOUS samples. cp.async pool (warp/sample) ->
//             coarse MLP CTA-cooperative -> refinement warp-per-sample.
//             Dynamic smem = 88 KB caps residency at 2 CTAs/SM -> grid 512 runs
//             in ~1.7 waves, so wave-2 pooling (DRAM) overlaps wave-1 MLP (L2/FMA).

#define EPS 1e-5f
#define BMAX 4096
#define DYN_SMEM_BYTES (88 * 1024)

__device__ int g_bound[BMAX + 1];

// ---------------- kernel 0: boundaries ----------------
__global__ void bounds_kernel(const int* __restrict__ seg, int N, int B) {
    int t = blockIdx.x * blockDim.x + threadIdx.x;
    int i = t * 4;
    if (i >= N) return;
    int vals[4];
    if (i + 4 <= N) {
        int4 v = *(const int4*)(seg + i);
        vals[0] = v.x; vals[1] = v.y; vals[2] = v.z; vals[3] = v.w;
    } else {
        for (int j = 0; j < 4; j++) vals[j] = (i + j < N) ? seg[i + j] : vals[j > 0 ? j - 1 : 0];
    }
    int prev = (i == 0) ? -1 : seg[i - 1];
    int lim = min(4, N - i);
    for (int j = 0; j < lim; j++) {
        int cur = vals[j];
        for (int b = prev + 1; b <= cur; b++) g_bound[b] = i + j;
        prev = cur;
    }
    if (i + 4 >= N)
        for (int b = prev + 1; b <= B; b++) g_bound[b] = N;
}

__device__ __forceinline__ float warpSum(float v) {
#pragma unroll
    for (int o = 16; o; o >>= 1) v += __shfl_xor_sync(0xffffffffu, v, o);
    return v;
}

__device__ __forceinline__ uint32_t smem_u32(const void* p) {
    uint32_t a;
    asm("{ .reg .u64 t; cvta.to.shared.u64 t, %1; cvt.u32.u64 %0, t; }" : "=r"(a) : "l"(p));
    return a;
}
__device__ __forceinline__ void cp_async16(uint32_t saddr, const void* gaddr) {
    asm volatile("cp.async.cg.shared.global [%0], [%1], 16;" :: "r"(saddr), "l"(gaddr));
}
#define CP_COMMIT() asm volatile("cp.async.commit_group;" ::)
#define CP_WAIT(n)  asm volatile("cp.async.wait_group %0;" :: "n"(n))

// ---------------- kernel 1: fused pool + MLP ----------------
__global__ __launch_bounds__(256) void fused_kernel(
    const float* __restrict__ feat, const int* __restrict__ cls,
    const float* __restrict__ cW1, const float* __restrict__ cb1,
    const float* __restrict__ cg1, const float* __restrict__ cbe1,
    const float* __restrict__ cW2, const float* __restrict__ cb2,
    const float* __restrict__ cg2, const float* __restrict__ cbe2,
    const float* __restrict__ cW3, const float* __restrict__ cb3,
    const float* __restrict__ rW1, const float* __restrict__ rb1,
    const float* __restrict__ rg1, const float* __restrict__ rbe1,
    const float* __restrict__ rW2, const float* __restrict__ rb2,
    const float* __restrict__ rg2, const float* __restrict__ rbe2,
    const float* __restrict__ rW3, const float* __restrict__ rb3,
    float* __restrict__ out, int B)
{
    extern __shared__ float dynsmem[];
    float* smem_all = dynsmem;                                    // 9216 floats: pool ring / MLP acts
    float (*sin_)[96] = reinterpret_cast<float(*)[96]>(dynsmem + 9216);   // 8 x 96
    float (*sstat)[2] = reinterpret_cast<float(*)[2]>(dynsmem + 9216 + 768); // 8 x 2

    const int tid = threadIdx.x, lane = tid & 31, w = tid >> 5;
    const int b = blockIdx.x * 8 + w;
    const bool valid = b < B;
    const int bc = valid ? b : B - 1;

    // ================= phase 1: cp.async mean pool (warp per sample) ========
    {
        const int start = g_bound[bc], end = g_bound[bc + 1];
        const int nr = end - start;
        const float* gsrc = feat + (size_t)start * 96;
        float* sb = smem_all + w * 1152;             // 3 bufs x 384 floats
        const uint32_t sb_u = smem_u32(sb);

        const int T = (nr + 3) >> 2;                 // 4-row chunks
        float a0 = 0.f, a1 = 0.f, a2 = 0.f;

        #define ISSUE(i)                                                              \
        {                                                                             \
            const int _i = (i);                                                       \
            const int _cnt = min(4, nr - _i * 4) * 24;                                \
            const uint32_t _sbase = sb_u + (uint32_t)(_i % 3) * 1536u;                \
            const float* _g = gsrc + (size_t)_i * 384;                                \
            if (lane < _cnt)      cp_async16(_sbase + lane * 16u,        _g + lane * 4);        \
            if (lane + 32 < _cnt) cp_async16(_sbase + (lane + 32) * 16u, _g + (lane + 32) * 4); \
            if (lane + 64 < _cnt) cp_async16(_sbase + (lane + 64) * 16u, _g + (lane + 64) * 4); \
            CP_COMMIT();                                                              \
        }

        if (T > 0) ISSUE(0);
        if (T > 1) ISSUE(1);
        if (T > 2) ISSUE(2);

        for (int i = 0; i < T; i++) {
            const int after = T - 1 - i;
            if (after >= 2)      CP_WAIT(2);
            else if (after == 1) CP_WAIT(1);
            else                 CP_WAIT(0);
            __syncwarp();

            const float* bp = sb + (i % 3) * 384;
            const int rows = min(4, nr - i * 4);
            if (rows == 4) {
#pragma unroll
                for (int r = 0; r < 4; r++) {
                    a0 += bp[r * 96 + lane];
                    a1 += bp[r * 96 + 32 + lane];
                    a2 += bp[r * 96 + 64 + lane];
                }
            } else {
                for (int r = 0; r < rows; r++) {
                    a0 += bp[r * 96 + lane];
                    a1 += bp[r * 96 + 32 + lane];
                    a2 += bp[r * 96 + 64 + lane];
                }
            }
            __syncwarp();
            if (i + 3 < T) ISSUE(i + 3);
        }
        #undef ISSUE

        const float inv = 1.f / fmaxf((float)nr, 1.f);
        sin_[w][lane]      = a0 * inv;
        sin_[w][lane + 32] = a1 * inv;
        sin_[w][lane + 64] = a2 * inv;
    }
    __syncthreads();

    float* actA = smem_all;          // 8 x 256
    float* actB = smem_all + 2048;   // 8 x 128
    #define ACTA(s, f) actA[(s) * 256 + (f)]
    #define ACTB(s, f) actB[(s) * 128 + (f)]

    // ================= phase 2: coarse L1 (96 -> 256), CTA-cooperative =====
    float acc[8];
    {
        const int f = tid;
        const float bv = cb1[f];
#pragma unroll
        for (int s = 0; s < 8; s++) acc[s] = bv;
#pragma unroll 2
        for (int c = 0; c < 96; c += 4) {
            float w0 = cW1[(c + 0) * 256 + f];
            float w1 = cW1[(c + 1) * 256 + f];
            float w2 = cW1[(c + 2) * 256 + f];
            float w3 = cW1[(c + 3) * 256 + f];
#pragma unroll
            for (int s = 0; s < 8; s++) {
                float4 x = *(const float4*)(&sin_[s][c]);
                acc[s] = fmaf(x.x, w0, acc[s]);
                acc[s] = fmaf(x.y, w1, acc[s]);
                acc[s] = fmaf(x.z, w2, acc[s]);
                acc[s] = fmaf(x.w, w3, acc[s]);
            }
        }
#pragma unroll
        for (int s = 0; s < 8; s++) ACTA(s, f) = acc[s];
    }
    __syncthreads();
    {   // stats for sample w over 256 features
        float sum = 0.f, sq = 0.f;
#pragma unroll
        for (int j = 0; j < 8; j++) {
            float x = ACTA(w, lane + 32 * j);
            sum += x; sq = fmaf(x, x, sq);
        }
        sum = warpSum(sum); sq = warpSum(sq);
        if (lane == 0) {
            float m = sum * (1.f / 256.f);
            float v = sq * (1.f / 256.f) - m * m;
            sstat[w][0] = m; sstat[w][1] = rsqrtf(v + EPS);
        }
    }
    __syncthreads();
    {
        const int f = tid;
        const float g = cg1[f], e = cbe1[f];
#pragma unroll
        for (int s = 0; s < 8; s++) {
            float m = sstat[s][0], r = sstat[s][1];
            ACTA(s, f) = fmaxf(fmaf((acc[s] - m) * r, g, e), 0.f);
        }
    }
    __syncthreads();

    // ================= phase 3: coarse L2 (256 -> 128), CTA-cooperative ====
    float acc2[4];
    const int fL2 = tid & 127, sh = tid >> 7;
    {
        const float bv = cb2[fL2];
#pragma unroll
        for (int i = 0; i < 4; i++) acc2[i] = bv;
#pragma unroll 2
        for (int c = 0; c < 256; c += 4) {
            float w0 = cW2[(c + 0) * 128 + fL2];
            float w1 = cW2[(c + 1) * 128 + fL2];
            float w2 = cW2[(c + 2) * 128 + fL2];
            float w3 = cW2[(c + 3) * 128 + fL2];
#pragma unroll
            for (int i = 0; i < 4; i++) {
                float4 x = *(const float4*)(&ACTA(sh * 4 + i, c));
                acc2[i] = fmaf(x.x, w0, acc2[i]);
                acc2[i] = fmaf(x.y, w1, acc2[i]);
                acc2[i] = fmaf(x.z, w2, acc2[i]);
                acc2[i] = fmaf(x.w, w3, acc2[i]);
            }
        }
#pragma unroll
        for (int i = 0; i < 4; i++) ACTB(sh * 4 + i, fL2) = acc2[i];
    }
    __syncthreads();
    {   // stats for sample w over 128 features
        float sum = 0.f, sq = 0.f;
#pragma unroll
        for (int j = 0; j < 4; j++) {
            float x = ACTB(w, lane + 32 * j);
            sum += x; sq = fmaf(x, x, sq);
        }
        sum = warpSum(sum); sq = warpSum(sq);
        if (lane == 0) {
            float m = sum * (1.f / 128.f);
            float v = sq * (1.f / 128.f) - m * m;
            sstat[w][0] = m; sstat[w][1] = rsqrtf(v + EPS);
        }
    }
    __syncthreads();
    {
        const float g = cg2[fL2], e = cbe2[fL2];
#pragma unroll
        for (int i = 0; i < 4; i++) {
            int s = sh * 4 + i;
            float m = sstat[s][0], r = sstat[s][1];
            ACTB(s, fL2) = fmaxf(fmaf((acc2[i] - m) * r, g, e), 0.f);
        }
    }
    __syncthreads();

    // ================= phase 4: warp-per-sample — coarse L3 + refinement ===
    float p0 = 0.f, p1 = 0.f, p2 = 0.f;
#pragma unroll
    for (int t = 0; t < 4; t++) {
        int c = lane + 32 * t;
        float x = ACTB(w, c);
        p0 = fmaf(x, cW3[c * 3 + 0], p0);
        p1 = fmaf(x, cW3[c * 3 + 1], p1);
        p2 = fmaf(x, cW3[c * 3 + 2], p2);
    }
    p0 = warpSum(p0) + cb3[0];
    p1 = warpSum(p1) + cb3[1];
    p2 = warpSum(p2) + cb3[2];

    const int k = cls[bc];
    const int f4 = lane * 4, f2 = lane * 2;

    // refine L1: 96 -> 128, LN, ReLU
    {
        const float* W = rW1 + k * 96 * 128;
        float4 bb = *(const float4*)(rb1 + k * 128 + f4);
        float B0[4] = {bb.x, bb.y, bb.z, bb.w};
#pragma unroll 2
        for (int c = 0; c < 96; c += 4) {
            float4 x = *(const float4*)(&sin_[w][c]);
            float4 wv;
            wv = *(const float4*)(W + (c + 0) * 128 + f4);
            B0[0] = fmaf(x.x, wv.x, B0[0]); B0[1] = fmaf(x.x, wv.y, B0[1]);
            B0[2] = fmaf(x.x, wv.z, B0[2]); B0[3] = fmaf(x.x, wv.w, B0[3]);
            wv = *(const float4*)(W + (c + 1) * 128 + f4);
            B0[0] = fmaf(x.y, wv.x, B0[0]); B0[1] = fmaf(x.y, wv.y, B0[1]);
            B0[2] = fmaf(x.y, wv.z, B0[2]); B0[3] = fmaf(x.y, wv.w, B0[3]);
            wv = *(const float4*)(W + (c + 2) * 128 + f4);
            B0[0] = fmaf(x.z, wv.x, B0[0]); B0[1] = fmaf(x.z, wv.y, B0[1]);
            B0[2] = fmaf(x.z, wv.z, B0[2]); B0[3] = fmaf(x.z, wv.w, B0[3]);
            wv = *(const float4*)(W + (c + 3) * 128 + f4);
            B0[0] = fmaf(x.w, wv.x, B0[0]); B0[1] = fmaf(x.w, wv.y, B0[1]);
            B0[2] = fmaf(x.w, wv.z, B0[2]); B0[3] = fmaf(x.w, wv.w, B0[3]);
        }
        float m = warpSum(B0[0] + B0[1] + B0[2] + B0[3]) * (1.f / 128.f);
        float v = 0.f;
#pragma unroll
        for (int j = 0; j < 4; j++) { float d = B0[j] - m; v = fmaf(d, d, v); }
        float r = rsqrtf(warpSum(v) * (1.f / 128.f) + EPS);
        float4 g = *(const float4*)(rg1 + k * 128 + f4);
        float4 e = *(const float4*)(rbe1 + k * 128 + f4);
        float4 o;
        o.x = fmaxf(fmaf((B0[0] - m) * r, g.x, e.x), 0.f);
        o.y = fmaxf(fmaf((B0[1] - m) * r, g.y, e.y), 0.f);
        o.z = fmaxf(fmaf((B0[2] - m) * r, g.z, e.z), 0.f);
        o.w = fmaxf(fmaf((B0[3] - m) * r, g.w, e.w), 0.f);
        *(float4*)(&ACTA(w, f4)) = o;
    }
    __syncwarp();

    // refine L2: 128 -> 64, LN, ReLU
    {
        const float* W = rW2 + k * 128 * 64;
        float2 bb = *(const float2*)(rb2 + k * 64 + f2);
        float D0[2] = {bb.x, bb.y};
#pragma unroll 2
        for (int c = 0; c < 128; c += 4) {
            float4 x = *(const float4*)(&ACTA(w, c));
            float2 wv;
            wv = *(const float2*)(W + (c + 0) * 64 + f2);
            D0[0] = fmaf(x.x, wv.x, D0[0]); D0[1] = fmaf(x.x, wv.y, D0[1]);
            wv = *(const float2*)(W + (c + 1) * 64 + f2);
            D0[0] = fmaf(x.y, wv.x, D0[0]); D0[1] = fmaf(x.y, wv.y, D0[1]);
            wv = *(const float2*)(W + (c + 2) * 64 + f2);
            D0[0] = fmaf(x.z, wv.x, D0[0]); D0[1] = fmaf(x.z, wv.y, D0[1]);
            wv = *(const float2*)(W + (c + 3) * 64 + f2);
            D0[0] = fmaf(x.w, wv.x, D0[0]); D0[1] = fmaf(x.w, wv.y, D0[1]);
        }
        float m = warpSum(D0[0] + D0[1]) * (1.f / 64.f);
        float d0 = D0[0] - m, d1 = D0[1] - m;
        float r = rsqrtf(warpSum(d0 * d0 + d1 * d1) * (1.f / 64.f) + EPS);
        float2 g = *(const float2*)(rg2 + k * 64 + f2);
        float2 e = *(const float2*)(rbe2 + k * 64 + f2);
        float2 o;
        o.x = fmaxf(fmaf(d0 * r, g.x, e.x), 0.f);
        o.y = fmaxf(fmaf(d1 * r, g.y, e.y), 0.f);
        *(float2*)(&ACTB(w, f2)) = o;
    }
    __syncwarp();

    // refine L3: 64 -> 3, add coarse, write out
    {
        const float* W3 = rW3 + k * 192;
        float q0 = 0.f, q1 = 0.f, q2 = 0.f;
#pragma unroll
        for (int t = 0; t < 2; t++) {
            int c = lane + 32 * t;
            float x = ACTB(w, c);
            q0 = fmaf(x, W3[c * 3 + 0], q0);
            q1 = fmaf(x, W3[c * 3 + 1], q1);
            q2 = fmaf(x, W3[c * 3 + 2], q2);
        }
        q0 = warpSum(q0) + rb3[k * 3 + 0];
        q1 = warpSum(q1) + rb3[k * 3 + 1];
        q2 = warpSum(q2) + rb3[k * 3 + 2];

        if (valid && lane < 3) {
            float pc = (lane == 0) ? p0 : (lane == 1) ? p1 : p2;
            float qc = (lane == 0) ? q0 : (lane == 1) ? q1 : q2;
            out[b * 3 + lane] = pc + qc;
        }
    }
    #undef ACTA
    #undef ACTB
}

// ---------------- launch ----------------
extern "C" void kernel_launch(void* const* d_in, const int* in_sizes, int n_in,
                              void* d_out, int out_size) {
    const float* feat = (const float*)d_in[0];
    const int*   seg  = (const int*)d_in[1];
    const int*   cls  = (const int*)d_in[2];
    const int N = in_sizes[1];
    const int B = in_sizes[2];

    // occupancy cap: 88 KB dynamic smem -> 2 CTAs/SM -> ~1.7 waves for grid 512
    cudaFuncSetAttribute(fused_kernel, cudaFuncAttributeMaxDynamicSharedMemorySize,
                         DYN_SMEM_BYTES);

    bounds_kernel<<<(N / 4 + 255) / 256, 256>>>(seg, N, B);
    fused_kernel<<<(B + 7) / 8, 256, DYN_SMEM_BYTES>>>(
        feat, cls,
        (const float*)d_in[3],  (const float*)d_in[4],  (const float*)d_in[5],  (const float*)d_in[6],
        (const float*)d_in[7],  (const float*)d_in[8],  (const float*)d_in[9],  (const float*)d_in[10],
        (const float*)d_in[11], (const float*)d_in[12],
        (const float*)d_in[13], (const float*)d_in[14], (const float*)d_in[15], (const float*)d_in[16],
        (const float*)d_in[17], (const float*)d_in[18], (const float*)d_in[19], (const float*)d_in[20],
        (const float*)d_in[21], (const float*)d_in[22],
        (float*)d_out, B);
}

// round 11
// speedup vs baseline: 1.4653x; 1.4653x over previous
#include <cuda_runtime.h>
#include <cstdint>

// VoxelBracketPredictor_v2 — 2-kernel pipeline (R8 + class-windowed refinement):
//  k0 bounds: segment boundaries (int4 scan of sorted segment_ids)
//  k1 fused:  CTA = 8 CONTIGUOUS samples. cp.async pool (warp/sample) ->
//             coarse MLP CTA-cooperative -> refinement warp-per-sample but
//             executed in 4 class WINDOWS (barrier-delimited): all warps on the
//             SM touching head k run together -> 80KB head weights go L1-resident,
//             refine L2 traffic drops ~5x.

#define EPS 1e-5f
#define BMAX 4096

__device__ int g_bound[BMAX + 1];

// ---------------- kernel 0: boundaries ----------------
__global__ void bounds_kernel(const int* __restrict__ seg, int N, int B) {
    int t = blockIdx.x * blockDim.x + threadIdx.x;
    int i = t * 4;
    if (i >= N) return;
    int vals[4];
    if (i + 4 <= N) {
        int4 v = *(const int4*)(seg + i);
        vals[0] = v.x; vals[1] = v.y; vals[2] = v.z; vals[3] = v.w;
    } else {
        for (int j = 0; j < 4; j++) vals[j] = (i + j < N) ? seg[i + j] : vals[j > 0 ? j - 1 : 0];
    }
    int prev = (i == 0) ? -1 : seg[i - 1];
    int lim = min(4, N - i);
    for (int j = 0; j < lim; j++) {
        int cur = vals[j];
        for (int b = prev + 1; b <= cur; b++) g_bound[b] = i + j;
        prev = cur;
    }
    if (i + 4 >= N)
        for (int b = prev + 1; b <= B; b++) g_bound[b] = N;
}

__device__ __forceinline__ float warpSum(float v) {
#pragma unroll
    for (int o = 16; o; o >>= 1) v += __shfl_xor_sync(0xffffffffu, v, o);
    return v;
}

__device__ __forceinline__ uint32_t smem_u32(const void* p) {
    uint32_t a;
    asm("{ .reg .u64 t; cvta.to.shared.u64 t, %1; cvt.u32.u64 %0, t; }" : "=r"(a) : "l"(p));
    return a;
}
__device__ __forceinline__ void cp_async16(uint32_t saddr, const void* gaddr) {
    asm volatile("cp.async.cg.shared.global [%0], [%1], 16;" :: "r"(saddr), "l"(gaddr));
}
#define CP_COMMIT() asm volatile("cp.async.commit_group;" ::)
#define CP_WAIT(n)  asm volatile("cp.async.wait_group %0;" :: "n"(n))

// ---------------- kernel 1: fused pool + MLP ----------------
__global__ __launch_bounds__(256) void fused_kernel(
    const float* __restrict__ feat, const int* __restrict__ cls,
    const float* __restrict__ cW1, const float* __restrict__ cb1,
    const float* __restrict__ cg1, const float* __restrict__ cbe1,
    const float* __restrict__ cW2, const float* __restrict__ cb2,
    const float* __restrict__ cg2, const float* __restrict__ cbe2,
    const float* __restrict__ cW3, const float* __restrict__ cb3,
    const float* __restrict__ rW1, const float* __restrict__ rb1,
    const float* __restrict__ rg1, const float* __restrict__ rbe1,
    const float* __restrict__ rW2, const float* __restrict__ rb2,
    const float* __restrict__ rg2, const float* __restrict__ rbe2,
    const float* __restrict__ rW3, const float* __restrict__ rb3,
    float* __restrict__ out, int B)
{
    __shared__ float smem_all[9216];     // pool ring (8 warps x 3 x 384) / MLP acts
    __shared__ float sin_[8][96];        // pooled inputs
    __shared__ float sstat[8][2];

    const int tid = threadIdx.x, lane = tid & 31, w = tid >> 5;
    const int b = blockIdx.x * 8 + w;
    const bool valid = b < B;
    const int bc = valid ? b : B - 1;

    // ================= phase 1: cp.async mean pool (warp per sample) ========
    {
        const int start = g_bound[bc], end = g_bound[bc + 1];
        const int nr = end - start;
        const float* gsrc = feat + (size_t)start * 96;
        float* sb = smem_all + w * 1152;             // 3 bufs x 384 floats
        const uint32_t sb_u = smem_u32(sb);

        const int T = (nr + 3) >> 2;                 // 4-row chunks
        float a0 = 0.f, a1 = 0.f, a2 = 0.f;

        #define ISSUE(i)                                                              \
        {                                                                             \
            const int _i = (i);                                                       \
            const int _cnt = min(4, nr - _i * 4) * 24;                                \
            const uint32_t _sbase = sb_u + (uint32_t)(_i % 3) * 1536u;                \
            const float* _g = gsrc + (size_t)_i * 384;                                \
            if (lane < _cnt)      cp_async16(_sbase + lane * 16u,        _g + lane * 4);        \
            if (lane + 32 < _cnt) cp_async16(_sbase + (lane + 32) * 16u, _g + (lane + 32) * 4); \
            if (lane + 64 < _cnt) cp_async16(_sbase + (lane + 64) * 16u, _g + (lane + 64) * 4); \
            CP_COMMIT();                                                              \
        }

        if (T > 0) ISSUE(0);
        if (T > 1) ISSUE(1);
        if (T > 2) ISSUE(2);

        for (int i = 0; i < T; i++) {
            const int after = T - 1 - i;
            if (after >= 2)      CP_WAIT(2);
            else if (after == 1) CP_WAIT(1);
            else                 CP_WAIT(0);
            __syncwarp();

            const float* bp = sb + (i % 3) * 384;
            const int rows = min(4, nr - i * 4);
            if (rows == 4) {
#pragma unroll
                for (int r = 0; r < 4; r++) {
                    a0 += bp[r * 96 + lane];
                    a1 += bp[r * 96 + 32 + lane];
                    a2 += bp[r * 96 + 64 + lane];
                }
            } else {
                for (int r = 0; r < rows; r++) {
                    a0 += bp[r * 96 + lane];
                    a1 += bp[r * 96 + 32 + lane];
                    a2 += bp[r * 96 + 64 + lane];
                }
            }
            __syncwarp();
            if (i + 3 < T) ISSUE(i + 3);
        }
        #undef ISSUE

        const float inv = 1.f / fmaxf((float)nr, 1.f);
        sin_[w][lane]      = a0 * inv;
        sin_[w][lane + 32] = a1 * inv;
        sin_[w][lane + 64] = a2 * inv;
    }
    __syncthreads();

    float* actA = smem_all;          // 8 x 256
    float* actB = smem_all + 2048;   // 8 x 128
    #define ACTA(s, f) actA[(s) * 256 + (f)]
    #define ACTB(s, f) actB[(s) * 128 + (f)]

    // ================= phase 2: coarse L1 (96 -> 256), CTA-cooperative =====
    float acc[8];
    {
        const int f = tid;
        const float bv = cb1[f];
#pragma unroll
        for (int s = 0; s < 8; s++) acc[s] = bv;
#pragma unroll 2
        for (int c = 0; c < 96; c += 4) {
            float w0 = cW1[(c + 0) * 256 + f];
            float w1 = cW1[(c + 1) * 256 + f];
            float w2 = cW1[(c + 2) * 256 + f];
            float w3 = cW1[(c + 3) * 256 + f];
#pragma unroll
            for (int s = 0; s < 8; s++) {
                float4 x = *(const float4*)(&sin_[s][c]);
                acc[s] = fmaf(x.x, w0, acc[s]);
                acc[s] = fmaf(x.y, w1, acc[s]);
                acc[s] = fmaf(x.z, w2, acc[s]);
                acc[s] = fmaf(x.w, w3, acc[s]);
            }
        }
#pragma unroll
        for (int s = 0; s < 8; s++) ACTA(s, f) = acc[s];
    }
    __syncthreads();
    {   // stats for sample w over 256 features
        float sum = 0.f, sq = 0.f;
#pragma unroll
        for (int j = 0; j < 8; j++) {
            float x = ACTA(w, lane + 32 * j);
            sum += x; sq = fmaf(x, x, sq);
        }
        sum = warpSum(sum); sq = warpSum(sq);
        if (lane == 0) {
            float m = sum * (1.f / 256.f);
            float v = sq * (1.f / 256.f) - m * m;
            sstat[w][0] = m; sstat[w][1] = rsqrtf(v + EPS);
        }
    }
    __syncthreads();
    {
        const int f = tid;
        const float g = cg1[f], e = cbe1[f];
#pragma unroll
        for (int s = 0; s < 8; s++) {
            float m = sstat[s][0], r = sstat[s][1];
            ACTA(s, f) = fmaxf(fmaf((acc[s] - m) * r, g, e), 0.f);
        }
    }
    __syncthreads();

    // ================= phase 3: coarse L2 (256 -> 128), CTA-cooperative ====
    float acc2[4];
    const int fL2 = tid & 127, sh = tid >> 7;
    {
        const float bv = cb2[fL2];
#pragma unroll
        for (int i = 0; i < 4; i++) acc2[i] = bv;
#pragma unroll 2
        for (int c = 0; c < 256; c += 4) {
            float w0 = cW2[(c + 0) * 128 + fL2];
            float w1 = cW2[(c + 1) * 128 + fL2];
            float w2 = cW2[(c + 2) * 128 + fL2];
            float w3 = cW2[(c + 3) * 128 + fL2];
#pragma unroll
            for (int i = 0; i < 4; i++) {
                float4 x = *(const float4*)(&ACTA(sh * 4 + i, c));
                acc2[i] = fmaf(x.x, w0, acc2[i]);
                acc2[i] = fmaf(x.y, w1, acc2[i]);
                acc2[i] = fmaf(x.z, w2, acc2[i]);
                acc2[i] = fmaf(x.w, w3, acc2[i]);
            }
        }
#pragma unroll
        for (int i = 0; i < 4; i++) ACTB(sh * 4 + i, fL2) = acc2[i];
    }
    __syncthreads();
    {   // stats for sample w over 128 features
        float sum = 0.f, sq = 0.f;
#pragma unroll
        for (int j = 0; j < 4; j++) {
            float x = ACTB(w, lane + 32 * j);
            sum += x; sq = fmaf(x, x, sq);
        }
        sum = warpSum(sum); sq = warpSum(sq);
        if (lane == 0) {
            float m = sum * (1.f / 128.f);
            float v = sq * (1.f / 128.f) - m * m;
            sstat[w][0] = m; sstat[w][1] = rsqrtf(v + EPS);
        }
    }
    __syncthreads();
    {
        const float g = cg2[fL2], e = cbe2[fL2];
#pragma unroll
        for (int i = 0; i < 4; i++) {
            int s = sh * 4 + i;
            float m = sstat[s][0], r = sstat[s][1];
            ACTB(s, fL2) = fmaxf(fmaf((acc2[i] - m) * r, g, e), 0.f);
        }
    }
    __syncthreads();

    // ================= phase 4: coarse L3 (warp-per-sample) ================
    float p0 = 0.f, p1 = 0.f, p2 = 0.f;
#pragma unroll
    for (int t = 0; t < 4; t++) {
        int c = lane + 32 * t;
        float x = ACTB(w, c);
        p0 = fmaf(x, cW3[c * 3 + 0], p0);
        p1 = fmaf(x, cW3[c * 3 + 1], p1);
        p2 = fmaf(x, cW3[c * 3 + 2], p2);
    }
    p0 = warpSum(p0) + cb3[0];
    p1 = warpSum(p1) + cb3[1];
    p2 = warpSum(p2) + cb3[2];

    const int k = cls[bc];
    const int f4 = lane * 4, f2 = lane * 2;

    // ================= phase 5: refinement in 4 class windows ==============
    // Window kk: only warps whose sample is class kk run; all active warps on
    // the SM stream the SAME 80KB head -> L1-resident. Barriers delimit windows.
    __syncthreads();
#pragma unroll
    for (int kk = 0; kk < 4; kk++) {
        if (k == kk) {
            // ---- refine L1: 96 -> 128, LN, ReLU ----
            {
                const float* W = rW1 + kk * 96 * 128;
                float4 bb = *(const float4*)(rb1 + kk * 128 + f4);
                float B0[4] = {bb.x, bb.y, bb.z, bb.w};
#pragma unroll 2
                for (int c = 0; c < 96; c += 4) {
                    float4 x = *(const float4*)(&sin_[w][c]);
                    float4 wv;
                    wv = *(const float4*)(W + (c + 0) * 128 + f4);
                    B0[0] = fmaf(x.x, wv.x, B0[0]); B0[1] = fmaf(x.x, wv.y, B0[1]);
                    B0[2] = fmaf(x.x, wv.z, B0[2]); B0[3] = fmaf(x.x, wv.w, B0[3]);
                    wv = *(const float4*)(W + (c + 1) * 128 + f4);
                    B0[0] = fmaf(x.y, wv.x, B0[0]); B0[1] = fmaf(x.y, wv.y, B0[1]);
                    B0[2] = fmaf(x.y, wv.z, B0[2]); B0[3] = fmaf(x.y, wv.w, B0[3]);
                    wv = *(const float4*)(W + (c + 2) * 128 + f4);
                    B0[0] = fmaf(x.z, wv.x, B0[0]); B0[1] = fmaf(x.z, wv.y, B0[1]);
                    B0[2] = fmaf(x.z, wv.z, B0[2]); B0[3] = fmaf(x.z, wv.w, B0[3]);
                    wv = *(const float4*)(W + (c + 3) * 128 + f4);
                    B0[0] = fmaf(x.w, wv.x, B0[0]); B0[1] = fmaf(x.w, wv.y, B0[1]);
                    B0[2] = fmaf(x.w, wv.z, B0[2]); B0[3] = fmaf(x.w, wv.w, B0[3]);
                }
                float m = warpSum(B0[0] + B0[1] + B0[2] + B0[3]) * (1.f / 128.f);
                float v = 0.f;
#pragma unroll
                for (int j = 0; j < 4; j++) { float d = B0[j] - m; v = fmaf(d, d, v); }
                float r = rsqrtf(warpSum(v) * (1.f / 128.f) + EPS);
                float4 g = *(const float4*)(rg1 + kk * 128 + f4);
                float4 e = *(const float4*)(rbe1 + kk * 128 + f4);
                float4 o;
                o.x = fmaxf(fmaf((B0[0] - m) * r, g.x, e.x), 0.f);
                o.y = fmaxf(fmaf((B0[1] - m) * r, g.y, e.y), 0.f);
                o.z = fmaxf(fmaf((B0[2] - m) * r, g.z, e.z), 0.f);
                o.w = fmaxf(fmaf((B0[3] - m) * r, g.w, e.w), 0.f);
                *(float4*)(&ACTA(w, f4)) = o;
            }
            __syncwarp();

            // ---- refine L2: 128 -> 64, LN, ReLU ----
            {
                const float* W = rW2 + kk * 128 * 64;
                float2 bb = *(const float2*)(rb2 + kk * 64 + f2);
                float D0[2] = {bb.x, bb.y};
#pragma unroll 2
                for (int c = 0; c < 128; c += 4) {
                    float4 x = *(const float4*)(&ACTA(w, c));
                    float2 wv;
                    wv = *(const float2*)(W + (c + 0) * 64 + f2);
                    D0[0] = fmaf(x.x, wv.x, D0[0]); D0[1] = fmaf(x.x, wv.y, D0[1]);
                    wv = *(const float2*)(W + (c + 1) * 64 + f2);
                    D0[0] = fmaf(x.y, wv.x, D0[0]); D0[1] = fmaf(x.y, wv.y, D0[1]);
                    wv = *(const float2*)(W + (c + 2) * 64 + f2);
                    D0[0] = fmaf(x.z, wv.x, D0[0]); D0[1] = fmaf(x.z, wv.y, D0[1]);
                    wv = *(const float2*)(W + (c + 3) * 64 + f2);
                    D0[0] = fmaf(x.w, wv.x, D0[0]); D0[1] = fmaf(x.w, wv.y, D0[1]);
                }
                float m = warpSum(D0[0] + D0[1]) * (1.f / 64.f);
                float d0 = D0[0] - m, d1 = D0[1] - m;
                float r = rsqrtf(warpSum(d0 * d0 + d1 * d1) * (1.f / 64.f) + EPS);
                float2 g = *(const float2*)(rg2 + kk * 64 + f2);
                float2 e = *(const float2*)(rbe2 + kk * 64 + f2);
                float2 o;
                o.x = fmaxf(fmaf(d0 * r, g.x, e.x), 0.f);
                o.y = fmaxf(fmaf(d1 * r, g.y, e.y), 0.f);
                *(float2*)(&ACTB(w, f2)) = o;
            }
            __syncwarp();

            // ---- refine L3: 64 -> 3, add coarse, write out ----
            {
                const float* W3 = rW3 + kk * 192;
                float q0 = 0.f, q1 = 0.f, q2 = 0.f;
#pragma unroll
                for (int t = 0; t < 2; t++) {
                    int c = lane + 32 * t;
                    float x = ACTB(w, c);
                    q0 = fmaf(x, W3[c * 3 + 0], q0);
                    q1 = fmaf(x, W3[c * 3 + 1], q1);
                    q2 = fmaf(x, W3[c * 3 + 2], q2);
                }
                q0 = warpSum(q0) + rb3[kk * 3 + 0];
                q1 = warpSum(q1) + rb3[kk * 3 + 1];
                q2 = warpSum(q2) + rb3[kk * 3 + 2];

                if (valid && lane < 3) {
                    float pc = (lane == 0) ? p0 : (lane == 1) ? p1 : p2;
                    float qc = (lane == 0) ? q0 : (lane == 1) ? q1 : q2;
                    out[b * 3 + lane] = pc + qc;
                }
            }
        }
        __syncthreads();
    }
    #undef ACTA
    #undef ACTB
}

// ---------------- launch ----------------
extern "C" void kernel_launch(void* const* d_in, const int* in_sizes, int n_in,
                              void* d_out, int out_size) {
    const float* feat = (const float*)d_in[0];
    const int*   seg  = (const int*)d_in[1];
    const int*   cls  = (const int*)d_in[2];
    const int N = in_sizes[1];
    const int B = in_sizes[2];

    bounds_kernel<<<(N / 4 + 255) / 256, 256>>>(seg, N, B);
    fused_kernel<<<(B + 7) / 8, 256>>>(
        feat, cls,
        (const float*)d_in[3],  (const float*)d_in[4],  (const float*)d_in[5],  (const float*)d_in[6],
        (const float*)d_in[7],  (const float*)d_in[8],  (const float*)d_in[9],  (const float*)d_in[10],
        (const float*)d_in[11], (const float*)d_in[12],
        (const float*)d_in[13], (const float*)d_in[14], (const float*)d_in[15], (const float*)d_in[16],
        (const float*)d_in[17], (const float*)d_in[18], (const float*)d_in[19], (const float*)d_in[20],
        (const float*)d_in[21], (const float*)d_in[22],
        (float*)d_out, B);
}

// round 12
// speedup vs baseline: 1.7769x; 1.2126x over previous
#include <cuda_runtime.h>
#include <cstdint>

// VoxelBracketPredictor_v2 — ONE fused kernel (R8 + in-kernel segment search +
// refine-L1 hoisted into the coarse-L1 window):
//  CTA = 8 CONTIGUOUS samples, 256 threads.
//  - segment bounds: warp-cooperative 32-ary lower_bound (no bounds kernel)
//  - pool: cp.async ring, warp per sample (DRAM-saturating)
//  - coarse MLP: CTA-cooperative
//  - refine L1 (60% of refine weight bytes) computed warp-autonomously INSIDE
//    the coarse-L1 phase (LN via shuffles) -> its L2 latency hides under coarse
//    work; only refine L2+L3 remain in the tail.

#define EPS 1e-5f

__device__ __forceinline__ float warpSum(float v) {
#pragma unroll
    for (int o = 16; o; o >>= 1) v += __shfl_xor_sync(0xffffffffu, v, o);
    return v;
}

// warp-cooperative lower_bound: first idx with seg[idx] >= v, over sorted seg[0..N)
__device__ __forceinline__ int lb32(const int* __restrict__ seg, int N, int v, int lane) {
    int lo = 0, hi = N;
    while (hi - lo > 32) {
        const int span = hi - lo;
        const int pos = lo + (int)(((long long)span * lane) >> 5);   // lane0 -> lo
        const int val = seg[pos];
        const unsigned m = __ballot_sync(0xffffffffu, val < v);
        if (m == 0) return lo;                      // seg[lo] >= v -> answer == lo
        const int j = 31 - __clz(m);                // highest lane with val < v
        const int pos_j  = __shfl_sync(0xffffffffu, pos, j);
        const int pos_j1 = (j < 31) ? __shfl_sync(0xffffffffu, pos, j + 1) : hi;
        lo = pos_j + 1;
        hi = pos_j1;
    }
    const int pos = lo + lane;
    const int val = (pos < hi) ? seg[pos] : 0x7fffffff;
    const unsigned m = __ballot_sync(0xffffffffu, (pos < hi) && (val < v));
    return lo + __popc(m);
}

__device__ __forceinline__ uint32_t smem_u32(const void* p) {
    uint32_t a;
    asm("{ .reg .u64 t; cvta.to.shared.u64 t, %1; cvt.u32.u64 %0, t; }" : "=r"(a) : "l"(p));
    return a;
}
__device__ __forceinline__ void cp_async16(uint32_t saddr, const void* gaddr) {
    asm volatile("cp.async.cg.shared.global [%0], [%1], 16;" :: "r"(saddr), "l"(gaddr));
}
#define CP_COMMIT() asm volatile("cp.async.commit_group;" ::)
#define CP_WAIT(n)  asm volatile("cp.async.wait_group %0;" :: "n"(n))

__global__ __launch_bounds__(256) void fused_kernel(
    const float* __restrict__ feat, const int* __restrict__ seg,
    const int* __restrict__ cls,
    const float* __restrict__ cW1, const float* __restrict__ cb1,
    const float* __restrict__ cg1, const float* __restrict__ cbe1,
    const float* __restrict__ cW2, const float* __restrict__ cb2,
    const float* __restrict__ cg2, const float* __restrict__ cbe2,
    const float* __restrict__ cW3, const float* __restrict__ cb3,
    const float* __restrict__ rW1, const float* __restrict__ rb1,
    const float* __restrict__ rg1, const float* __restrict__ rbe1,
    const float* __restrict__ rW2, const float* __restrict__ rb2,
    const float* __restrict__ rg2, const float* __restrict__ rbe2,
    const float* __restrict__ rW3, const float* __restrict__ rb3,
    float* __restrict__ out, int N, int B)
{
    __shared__ float smem_all[9216];   // pool ring (8w x 3 x 384) / actA+actB+refC
    __shared__ float sin_[8][96];      // pooled inputs
    __shared__ float sstat[8][2];
    __shared__ int   sbound[9];

    const int tid = threadIdx.x, lane = tid & 31, w = tid >> 5;
    const int b8 = blockIdx.x * 8;
    const int b = b8 + w;
    const bool valid = b < B;
    const int bc = valid ? b : B - 1;
    const int k = cls[bc];             // routed refinement head (warp-uniform)

    // ============ phase 0: segment bounds via warp 32-ary search ============
    {
        int s = lb32(seg, N, min(b8 + w, B), lane);
        if (lane == 0) sbound[w] = s;
        if (w == 0) {
            int s8 = lb32(seg, N, min(b8 + 8, B), lane);
            if (lane == 0) sbound[8] = s8;
        }
    }
    __syncthreads();

    // ================= phase 1: cp.async mean pool (warp per sample) ========
    {
        const int start = sbound[valid ? w : (B - 1 - b8)], // clamp only pathological
              end0 = sbound[valid ? (w + 1) : (B - b8)];
        const int st = valid ? start : sbound[w];           // (grid sized so valid always)
        const int en = valid ? end0 : sbound[w];
        const int nr = en - st;
        const float* gsrc = feat + (size_t)st * 96;
        float* sb = smem_all + w * 1152;             // 3 bufs x 384 floats
        const uint32_t sb_u = smem_u32(sb);

        const int T = (nr + 3) >> 2;                 // 4-row chunks
        float a0 = 0.f, a1 = 0.f, a2 = 0.f;

        #define ISSUE(i)                                                              \
        {                                                                             \
            const int _i = (i);                                                       \
            const int _cnt = min(4, nr - _i * 4) * 24;                                \
            const uint32_t _sbase = sb_u + (uint32_t)(_i % 3) * 1536u;                \
            const float* _g = gsrc + (size_t)_i * 384;                                \
            if (lane < _cnt)      cp_async16(_sbase + lane * 16u,        _g + lane * 4);        \
            if (lane + 32 < _cnt) cp_async16(_sbase + (lane + 32) * 16u, _g + (lane + 32) * 4); \
            if (lane + 64 < _cnt) cp_async16(_sbase + (lane + 64) * 16u, _g + (lane + 64) * 4); \
            CP_COMMIT();                                                              \
        }

        if (T > 0) ISSUE(0);
        if (T > 1) ISSUE(1);
        if (T > 2) ISSUE(2);

        for (int i = 0; i < T; i++) {
            const int after = T - 1 - i;
            if (after >= 2)      CP_WAIT(2);
            else if (after == 1) CP_WAIT(1);
            else                 CP_WAIT(0);
            __syncwarp();

            const float* bp = sb + (i % 3) * 384;
            const int rows = min(4, nr - i * 4);
            if (rows == 4) {
#pragma unroll
                for (int r = 0; r < 4; r++) {
                    a0 += bp[r * 96 + lane];
                    a1 += bp[r * 96 + 32 + lane];
                    a2 += bp[r * 96 + 64 + lane];
                }
            } else {
                for (int r = 0; r < rows; r++) {
                    a0 += bp[r * 96 + lane];
                    a1 += bp[r * 96 + 32 + lane];
                    a2 += bp[r * 96 + 64 + lane];
                }
            }
            __syncwarp();
            if (i + 3 < T) ISSUE(i + 3);
        }
        #undef ISSUE

        const float inv = 1.f / fmaxf((float)nr, 1.f);
        sin_[w][lane]      = a0 * inv;
        sin_[w][lane + 32] = a1 * inv;
        sin_[w][lane + 64] = a2 * inv;
    }
    __syncthreads();

    float* actA = smem_all;          // 8 x 256
    float* actB = smem_all + 2048;   // 8 x 128
    float* refC = smem_all + 3072;   // 8 x 128 (refine L1 activations)
    #define ACTA(s, f) actA[(s) * 256 + (f)]
    #define ACTB(s, f) actB[(s) * 128 + (f)]

    const int f4 = lane * 4, f2 = lane * 2;

    // ======== phase 2a: coarse L1 matmul (CTA-cooperative, raw to ACTA) =====
    float acc[8];
    {
        const int f = tid;
        const float bv = cb1[f];
#pragma unroll
        for (int s = 0; s < 8; s++) acc[s] = bv;
#pragma unroll 2
        for (int c = 0; c < 96; c += 4) {
            float w0 = cW1[(c + 0) * 256 + f];
            float w1 = cW1[(c + 1) * 256 + f];
            float w2 = cW1[(c + 2) * 256 + f];
            float w3 = cW1[(c + 3) * 256 + f];
#pragma unroll
            for (int s = 0; s < 8; s++) {
                float4 x = *(const float4*)(&sin_[s][c]);
                acc[s] = fmaf(x.x, w0, acc[s]);
                acc[s] = fmaf(x.y, w1, acc[s]);
                acc[s] = fmaf(x.z, w2, acc[s]);
                acc[s] = fmaf(x.w, w3, acc[s]);
            }
        }
#pragma unroll
        for (int s = 0; s < 8; s++) ACTA(s, f) = acc[s];
    }

    // ======== phase 2b: refine L1 (warp-autonomous, hoisted before barrier) =
    // reads only sin_[w]; LN via shuffles; writes refC — no conflict with ACTA.
    {
        const float* W = rW1 + k * 96 * 128;
        float4 bb = *(const float4*)(rb1 + k * 128 + f4);
        float B0[4] = {bb.x, bb.y, bb.z, bb.w};
#pragma unroll 2
        for (int c = 0; c < 96; c += 4) {
            float4 x = *(const float4*)(&sin_[w][c]);
            float4 wv;
            wv = *(const float4*)(W + (c + 0) * 128 + f4);
            B0[0] = fmaf(x.x, wv.x, B0[0]); B0[1] = fmaf(x.x, wv.y, B0[1]);
            B0[2] = fmaf(x.x, wv.z, B0[2]); B0[3] = fmaf(x.x, wv.w, B0[3]);
            wv = *(const float4*)(W + (c + 1) * 128 + f4);
            B0[0] = fmaf(x.y, wv.x, B0[0]); B0[1] = fmaf(x.y, wv.y, B0[1]);
            B0[2] = fmaf(x.y, wv.z, B0[2]); B0[3] = fmaf(x.y, wv.w, B0[3]);
            wv = *(const float4*)(W + (c + 2) * 128 + f4);
            B0[0] = fmaf(x.z, wv.x, B0[0]); B0[1] = fmaf(x.z, wv.y, B0[1]);
            B0[2] = fmaf(x.z, wv.z, B0[2]); B0[3] = fmaf(x.z, wv.w, B0[3]);
            wv = *(const float4*)(W + (c + 3) * 128 + f4);
            B0[0] = fmaf(x.w, wv.x, B0[0]); B0[1] = fmaf(x.w, wv.y, B0[1]);
            B0[2] = fmaf(x.w, wv.z, B0[2]); B0[3] = fmaf(x.w, wv.w, B0[3]);
        }
        float m = warpSum(B0[0] + B0[1] + B0[2] + B0[3]) * (1.f / 128.f);
        float v = 0.f;
#pragma unroll
        for (int j = 0; j < 4; j++) { float d = B0[j] - m; v = fmaf(d, d, v); }
        float r = rsqrtf(warpSum(v) * (1.f / 128.f) + EPS);
        float4 g = *(const float4*)(rg1 + k * 128 + f4);
        float4 e = *(const float4*)(rbe1 + k * 128 + f4);
        float4 o;
        o.x = fmaxf(fmaf((B0[0] - m) * r, g.x, e.x), 0.f);
        o.y = fmaxf(fmaf((B0[1] - m) * r, g.y, e.y), 0.f);
        o.z = fmaxf(fmaf((B0[2] - m) * r, g.z, e.z), 0.f);
        o.w = fmaxf(fmaf((B0[3] - m) * r, g.w, e.w), 0.f);
        *(float4*)(&refC[w * 128 + f4]) = o;
    }
    __syncthreads();

    // ======== coarse L1 LN ========
    {
        float sum = 0.f, sq = 0.f;
#pragma unroll
        for (int j = 0; j < 8; j++) {
            float x = ACTA(w, lane + 32 * j);
            sum += x; sq = fmaf(x, x, sq);
        }
        sum = warpSum(sum); sq = warpSum(sq);
        if (lane == 0) {
            float m = sum * (1.f / 256.f);
            float v = sq * (1.f / 256.f) - m * m;
            sstat[w][0] = m; sstat[w][1] = rsqrtf(v + EPS);
        }
    }
    __syncthreads();
    {
        const int f = tid;
        const float g = cg1[f], e = cbe1[f];
#pragma unroll
        for (int s = 0; s < 8; s++) {
            float m = sstat[s][0], r = sstat[s][1];
            ACTA(s, f) = fmaxf(fmaf((acc[s] - m) * r, g, e), 0.f);
        }
    }
    __syncthreads();

    // ======== coarse L2 (256 -> 128), CTA-cooperative ========
    float acc2[4];
    const int fL2 = tid & 127, sh = tid >> 7;
    {
        const float bv = cb2[fL2];
#pragma unroll
        for (int i = 0; i < 4; i++) acc2[i] = bv;
#pragma unroll 2
        for (int c = 0; c < 256; c += 4) {
            float w0 = cW2[(c + 0) * 128 + fL2];
            float w1 = cW2[(c + 1) * 128 + fL2];
            float w2 = cW2[(c + 2) * 128 + fL2];
            float w3 = cW2[(c + 3) * 128 + fL2];
#pragma unroll
            for (int i = 0; i < 4; i++) {
                float4 x = *(const float4*)(&ACTA(sh * 4 + i, c));
                acc2[i] = fmaf(x.x, w0, acc2[i]);
                acc2[i] = fmaf(x.y, w1, acc2[i]);
                acc2[i] = fmaf(x.z, w2, acc2[i]);
                acc2[i] = fmaf(x.w, w3, acc2[i]);
            }
        }
#pragma unroll
        for (int i = 0; i < 4; i++) ACTB(sh * 4 + i, fL2) = acc2[i];
    }
    __syncthreads();
    {
        float sum = 0.f, sq = 0.f;
#pragma unroll
        for (int j = 0; j < 4; j++) {
            float x = ACTB(w, lane + 32 * j);
            sum += x; sq = fmaf(x, x, sq);
        }
        sum = warpSum(sum); sq = warpSum(sq);
        if (lane == 0) {
            float m = sum * (1.f / 128.f);
            float v = sq * (1.f / 128.f) - m * m;
            sstat[w][0] = m; sstat[w][1] = rsqrtf(v + EPS);
        }
    }
    __syncthreads();
    {
        const float g = cg2[fL2], e = cbe2[fL2];
#pragma unroll
        for (int i = 0; i < 4; i++) {
            int s = sh * 4 + i;
            float m = sstat[s][0], r = sstat[s][1];
            ACTB(s, fL2) = fmaxf(fmaf((acc2[i] - m) * r, g, e), 0.f);
        }
    }
    __syncthreads();

    // ======== coarse L3 (warp-per-sample) ========
    float p0 = 0.f, p1 = 0.f, p2 = 0.f;
#pragma unroll
    for (int t = 0; t < 4; t++) {
        int c = lane + 32 * t;
        float x = ACTB(w, c);
        p0 = fmaf(x, cW3[c * 3 + 0], p0);
        p1 = fmaf(x, cW3[c * 3 + 1], p1);
        p2 = fmaf(x, cW3[c * 3 + 2], p2);
    }
    p0 = warpSum(p0) + cb3[0];
    p1 = warpSum(p1) + cb3[1];
    p2 = warpSum(p2) + cb3[2];

    // ======== refine L2: 128 -> 64 (reads refC), LN, ReLU ========
    float r2out0, r2out1;
    {
        const float* W = rW2 + k * 128 * 64;
        const float* rin = refC + w * 128;
        float2 bb = *(const float2*)(rb2 + k * 64 + f2);
        float D0[2] = {bb.x, bb.y};
#pragma unroll 2
        for (int c = 0; c < 128; c += 4) {
            float4 x = *(const float4*)(&rin[c]);
            float2 wv;
            wv = *(const float2*)(W + (c + 0) * 64 + f2);
            D0[0] = fmaf(x.x, wv.x, D0[0]); D0[1] = fmaf(x.x, wv.y, D0[1]);
            wv = *(const float2*)(W + (c + 1) * 64 + f2);
            D0[0] = fmaf(x.y, wv.x, D0[0]); D0[1] = fmaf(x.y, wv.y, D0[1]);
            wv = *(const float2*)(W + (c + 2) * 64 + f2);
            D0[0] = fmaf(x.z, wv.x, D0[0]); D0[1] = fmaf(x.z, wv.y, D0[1]);
            wv = *(const float2*)(W + (c + 3) * 64 + f2);
            D0[0] = fmaf(x.w, wv.x, D0[0]); D0[1] = fmaf(x.w, wv.y, D0[1]);
        }
        float m = warpSum(D0[0] + D0[1]) * (1.f / 64.f);
        float d0 = D0[0] - m, d1 = D0[1] - m;
        float r = rsqrtf(warpSum(d0 * d0 + d1 * d1) * (1.f / 64.f) + EPS);
        float2 g = *(const float2*)(rg2 + k * 64 + f2);
        float2 e = *(const float2*)(rbe2 + k * 64 + f2);
        r2out0 = fmaxf(fmaf(d0 * r, g.x, e.x), 0.f);
        r2out1 = fmaxf(fmaf(d1 * r, g.y, e.y), 0.f);
    }
    __syncwarp();

    // ======== refine L3: 64 -> 3 via shuffles (activations in regs) ========
    {
        const float* W3 = rW3 + k * 192;
        // lane holds features f2, f2+1
        float q0 = r2out0 * W3[f2 * 3 + 0] + r2out1 * W3[(f2 + 1) * 3 + 0];
        float q1 = r2out0 * W3[f2 * 3 + 1] + r2out1 * W3[(f2 + 1) * 3 + 1];
        float q2 = r2out0 * W3[f2 * 3 + 2] + r2out1 * W3[(f2 + 1) * 3 + 2];
        q0 = warpSum(q0) + rb3[k * 3 + 0];
        q1 = warpSum(q1) + rb3[k * 3 + 1];
        q2 = warpSum(q2) + rb3[k * 3 + 2];

        if (valid && lane < 3) {
            float pc = (lane == 0) ? p0 : (lane == 1) ? p1 : p2;
            float qc = (lane == 0) ? q0 : (lane == 1) ? q1 : q2;
            out[b * 3 + lane] = pc + qc;
        }
    }
    #undef ACTA
    #undef ACTB
}

// ---------------- launch ----------------
extern "C" void kernel_launch(void* const* d_in, const int* in_sizes, int n_in,
                              void* d_out, int out_size) {
    const float* feat = (const float*)d_in[0];
    const int*   seg  = (const int*)d_in[1];
    const int*   cls  = (const int*)d_in[2];
    const int N = in_sizes[1];
    const int B = in_sizes[2];

    fused_kernel<<<(B + 7) / 8, 256>>>(
        feat, seg, cls,
        (const float*)d_in[3],  (const float*)d_in[4],  (const float*)d_in[5],  (const float*)d_in[6],
        (const float*)d_in[7],  (const float*)d_in[8],  (const float*)d_in[9],  (const float*)d_in[10],
        (const float*)d_in[11], (const float*)d_in[12],
        (const float*)d_in[13], (const float*)d_in[14], (const float*)d_in[15], (const float*)d_in[16],
        (const float*)d_in[17], (const float*)d_in[18], (const float*)d_in[19], (const float*)d_in[20],
        (const float*)d_in[21], (const float*)d_in[22],
        (float*)d_out, N, B);
}